// round 4
// baseline (speedup 1.0000x reference)
#include <cuda_runtime.h>
#include <cuda_pipeline.h>
#include <mma.h>
#include <math.h>

using namespace nvcuda;

#define B_  4
#define S_  2048
#define D_  2048
#define H_  16
#define DH_ 128

// Scratch (allocation-free rule: __device__ globals)
__device__ float g_qp[(size_t)B_ * S_ * D_];    // Q projection  [B*S, D]
__device__ float g_kp[(size_t)B_ * S_ * DH_];   // K projection  [B*S, DH]
__device__ float g_vp[(size_t)B_ * S_ * DH_];   // V projection  [B*S, DH]
__device__ float g_ao[(size_t)B_ * S_ * D_];    // attention out [B*S, D] (heads merged)

// ---------------------------------------------------------------------------
// Generic tf32 GEMM: C[M,N] = A[M,K] @ B[K,N] + bias[N]
// Block tile 128x64, K-chunk 32, 256 threads (8 warps, 4x2 warp grid).
// cp.async double-buffered mainloop.
// ---------------------------------------------------------------------------
#define GBM 128
#define GBN 64
#define GBK 32
#define GSTG (GBM * GBK + GBK * GBN)   // 6144 floats per stage

__global__ __launch_bounds__(256) void gemm_tf32(
    const float* __restrict__ A, const float* __restrict__ Bm,
    const float* __restrict__ bias, float* __restrict__ C,
    int M, int N, int K)
{
    __shared__ __align__(16) float smem[2 * GSTG];   // 48 KB; reused for epilogue

    const int tid  = threadIdx.x;
    const int warp = tid >> 5;
    const int wm   = warp & 3;
    const int wn   = warp >> 2;
    const int m0   = blockIdx.y * GBM;
    const int n0   = blockIdx.x * GBN;

    const int ar = tid >> 3, ac4 = tid & 7;
    const int br = tid >> 4, bc4 = tid & 15;

    auto prefetch = [&](int stage, int k0) {
        float* sA = smem + stage * GSTG;
        float* sB = sA + GBM * GBK;
        #pragma unroll
        for (int t = 0; t < 4; t++) {
            int r = ar + t * 32;
            __pipeline_memcpy_async(sA + r * GBK + ac4 * 4,
                                    A + (size_t)(m0 + r) * K + k0 + ac4 * 4, 16);
        }
        #pragma unroll
        for (int t = 0; t < 2; t++) {
            int r = br + t * 16;
            __pipeline_memcpy_async(sB + r * GBN + bc4 * 4,
                                    Bm + (size_t)(k0 + r) * N + n0 + bc4 * 4, 16);
        }
        __pipeline_commit();
    };

    wmma::fragment<wmma::accumulator, 16, 16, 8, float> c[2][2];
    #pragma unroll
    for (int i = 0; i < 2; i++)
        #pragma unroll
        for (int j = 0; j < 2; j++)
            wmma::fill_fragment(c[i][j], 0.0f);

    const int nIter = K / GBK;
    prefetch(0, 0);

    for (int it = 0; it < nIter; it++) {
        const int cur = it & 1;
        if (it + 1 < nIter) prefetch(cur ^ 1, (it + 1) * GBK);
        __pipeline_wait_prior((it + 1 < nIter) ? 1 : 0);
        __syncthreads();

        const float* sA = smem + cur * GSTG;
        const float* sB = sA + GBM * GBK;

        #pragma unroll
        for (int kk = 0; kk < GBK; kk += 8) {
            wmma::fragment<wmma::matrix_a, 16, 16, 8, wmma::precision::tf32, wmma::row_major> a[2];
            wmma::fragment<wmma::matrix_b, 16, 16, 8, wmma::precision::tf32, wmma::row_major> b[2];
            #pragma unroll
            for (int i = 0; i < 2; i++) {
                wmma::load_matrix_sync(a[i], sA + (wm * 32 + i * 16) * GBK + kk, GBK);
                #pragma unroll
                for (int e = 0; e < a[i].num_elements; e++)
                    a[i].x[e] = wmma::__float_to_tf32(a[i].x[e]);
            }
            #pragma unroll
            for (int j = 0; j < 2; j++) {
                wmma::load_matrix_sync(b[j], sB + kk * GBN + wn * 32 + j * 16, GBN);
                #pragma unroll
                for (int e = 0; e < b[j].num_elements; e++)
                    b[j].x[e] = wmma::__float_to_tf32(b[j].x[e]);
            }
            #pragma unroll
            for (int i = 0; i < 2; i++)
                #pragma unroll
                for (int j = 0; j < 2; j++)
                    wmma::mma_sync(c[i][j], a[i], b[j], c[i][j]);
        }
        __syncthreads();
    }

    #pragma unroll
    for (int i = 0; i < 2; i++)
        #pragma unroll
        for (int j = 0; j < 2; j++)
            wmma::store_matrix_sync(smem + (wm * 32 + i * 16) * GBN + wn * 32 + j * 16,
                                    c[i][j], GBN, wmma::mem_row_major);
    __syncthreads();
    #pragma unroll
    for (int t = 0; t < 8; t++) {
        int slot = tid + t * 256;
        int r = slot >> 4, c4 = slot & 15;
        float4 val = *(float4*)(smem + r * GBN + c4 * 4);
        const float* bp = bias + n0 + c4 * 4;
        val.x += bp[0]; val.y += bp[1]; val.z += bp[2]; val.w += bp[3];
        *(float4*)(C + (size_t)(m0 + r) * N + n0 + c4 * 4) = val;
    }
}

// ---------------------------------------------------------------------------
// Fused flash attention exploiting MQA: K/V shared across all H=16 heads.
// M-tile = 128 rows = 8 consecutive s x 16 heads. Because Qp rows are
// [S, H*DH] contiguous, the 128x128 Q tile IS the contiguous 8x2048 block:
//   flat si*2048 + h*128 + d == m*128 + d with m = si*16 + h.
// Streams 64-key K/V tiles; online softmax per row (rows independent even
// across heads); O alpha-scaled in smem and PV accumulates in place.
// ---------------------------------------------------------------------------
struct FASmem {
    float Q[128 * 128];   // 64 KB
    float K[64 * 128];    // 32 KB
    float V[64 * 128];    // 32 KB
    float S[128 * 64];    // 32 KB
    float O[128 * 128];   // 64 KB
    float m[128];
    float l[128];
    float alpha[128];
};                         // 230912 B total

__global__ __launch_bounds__(256) void fa_kernel(
    const float* __restrict__ Qp, const float* __restrict__ Kp,
    const float* __restrict__ Vp, float* __restrict__ AO)
{
    extern __shared__ __align__(16) char smraw[];
    FASmem& sm = *reinterpret_cast<FASmem*>(smraw);

    const int tid  = threadIdx.x;
    const int warp = tid >> 5;
    const int wm   = warp >> 1;   // 0..3 -> 32-row strip
    const int wn   = warp & 1;    // 0..1
    const int s0   = blockIdx.x * 8;    // 8 seq positions -> 128 (s,h) rows
    const int b    = blockIdx.y;
    const float scale = 0.08838834764831845f;   // 1/sqrt(128)

    const size_t qbase = (size_t)(b * S_ + s0) * D_;

    // Q tile: contiguous 8x2048 = 4096 float4 (pre-scaled); O zero-init
    #pragma unroll
    for (int t = 0; t < 16; t++) {
        int slot = tid + t * 256;
        float4 v4 = *(const float4*)(Qp + qbase + (size_t)slot * 4);
        v4.x *= scale; v4.y *= scale; v4.z *= scale; v4.w *= scale;
        *(float4*)(sm.Q + slot * 4) = v4;
        *(float4*)(sm.O + slot * 4) = make_float4(0.f, 0.f, 0.f, 0.f);
    }
    if (tid < 128) { sm.m[tid] = -INFINITY; sm.l[tid] = 0.0f; }
    __syncthreads();

    for (int kt = 0; kt < S_; kt += 64) {
        // stage K,V tiles: each 64x128 = 2048 float4, contiguous
        const size_t kvbase = (size_t)(b * S_ + kt) * DH_;
        #pragma unroll
        for (int t = 0; t < 8; t++) {
            int slot = tid + t * 256;
            *(float4*)(sm.K + slot * 4) = *(const float4*)(Kp + kvbase + (size_t)slot * 4);
            *(float4*)(sm.V + slot * 4) = *(const float4*)(Vp + kvbase + (size_t)slot * 4);
        }
        __syncthreads();

        // S = Q @ K^T : 128x64, warp tile 32x32 (4x2 grid), 2x2 frags
        {
            wmma::fragment<wmma::accumulator, 16, 16, 8, float> s[2][2];
            #pragma unroll
            for (int i = 0; i < 2; i++)
                #pragma unroll
                for (int j = 0; j < 2; j++)
                    wmma::fill_fragment(s[i][j], 0.0f);
            #pragma unroll
            for (int kk = 0; kk < 128; kk += 8) {
                wmma::fragment<wmma::matrix_a, 16, 16, 8, wmma::precision::tf32, wmma::row_major> a[2];
                #pragma unroll
                for (int i = 0; i < 2; i++) {
                    wmma::load_matrix_sync(a[i], sm.Q + (wm * 32 + i * 16) * 128 + kk, 128);
                    #pragma unroll
                    for (int e = 0; e < a[i].num_elements; e++)
                        a[i].x[e] = wmma::__float_to_tf32(a[i].x[e]);
                }
                #pragma unroll
                for (int j = 0; j < 2; j++) {
                    // K^T element (kdim, n) at sm.K[n*128 + kdim] -> col_major
                    wmma::fragment<wmma::matrix_b, 16, 16, 8, wmma::precision::tf32, wmma::col_major> bf;
                    wmma::load_matrix_sync(bf, sm.K + (wn * 32 + j * 16) * 128 + kk, 128);
                    #pragma unroll
                    for (int e = 0; e < bf.num_elements; e++)
                        bf.x[e] = wmma::__float_to_tf32(bf.x[e]);
                    #pragma unroll
                    for (int i = 0; i < 2; i++)
                        wmma::mma_sync(s[i][j], a[i], bf, s[i][j]);
                }
            }
            #pragma unroll
            for (int i = 0; i < 2; i++)
                #pragma unroll
                for (int j = 0; j < 2; j++)
                    wmma::store_matrix_sync(sm.S + (wm * 32 + i * 16) * 64 + wn * 32 + j * 16,
                                            s[i][j], 64, wmma::mem_row_major);
        }
        __syncthreads();

        // online softmax: 2 threads/row (warp-adjacent), shfl_xor reduction
        {
            const int row = tid >> 1, part = tid & 1;
            float* srow = sm.S + row * 64 + part * 32;
            float pm = -INFINITY;
            #pragma unroll
            for (int c = 0; c < 32; c++) pm = fmaxf(pm, srow[c]);
            pm = fmaxf(pm, __shfl_xor_sync(0xffffffffu, pm, 1));
            const float mold = sm.m[row];
            const float mnew = fmaxf(mold, pm);
            float psum = 0.f;
            #pragma unroll
            for (int c = 0; c < 32; c++) {
                float e = __expf(srow[c] - mnew);
                srow[c] = e;
                psum += e;
            }
            psum += __shfl_xor_sync(0xffffffffu, psum, 1);
            if (part == 0) {
                float al = __expf(mold - mnew);
                sm.alpha[row] = al;
                sm.l[row] = sm.l[row] * al + psum;
                sm.m[row] = mnew;
            }
        }
        __syncthreads();

        // O *= alpha(row)   (row = float4_index >> 5; 32 float4 per row)
        #pragma unroll
        for (int t = 0; t < 16; t++) {
            int slot = tid + t * 256;
            float al = sm.alpha[slot >> 5];
            float4 o4 = *(float4*)(sm.O + slot * 4);
            o4.x *= al; o4.y *= al; o4.z *= al; o4.w *= al;
            *(float4*)(sm.O + slot * 4) = o4;
        }
        __syncthreads();

        // O += P @ V : 128x128, warp tile 32x64 (4x2 grid), accumulate in place
        {
            wmma::fragment<wmma::accumulator, 16, 16, 8, float> o[2][4];
            #pragma unroll
            for (int i = 0; i < 2; i++)
                #pragma unroll
                for (int j = 0; j < 4; j++)
                    wmma::load_matrix_sync(o[i][j],
                        sm.O + (wm * 32 + i * 16) * 128 + wn * 64 + j * 16,
                        128, wmma::mem_row_major);
            #pragma unroll
            for (int kk = 0; kk < 64; kk += 8) {
                wmma::fragment<wmma::matrix_a, 16, 16, 8, wmma::precision::tf32, wmma::row_major> a[2];
                #pragma unroll
                for (int i = 0; i < 2; i++) {
                    wmma::load_matrix_sync(a[i], sm.S + (wm * 32 + i * 16) * 64 + kk, 64);
                    #pragma unroll
                    for (int e = 0; e < a[i].num_elements; e++)
                        a[i].x[e] = wmma::__float_to_tf32(a[i].x[e]);
                }
                #pragma unroll
                for (int j = 0; j < 4; j++) {
                    wmma::fragment<wmma::matrix_b, 16, 16, 8, wmma::precision::tf32, wmma::row_major> bf;
                    wmma::load_matrix_sync(bf, sm.V + kk * 128 + wn * 64 + j * 16, 128);
                    #pragma unroll
                    for (int e = 0; e < bf.num_elements; e++)
                        bf.x[e] = wmma::__float_to_tf32(bf.x[e]);
                    #pragma unroll
                    for (int i = 0; i < 2; i++)
                        wmma::mma_sync(o[i][j], a[i], bf, o[i][j]);
                }
            }
            #pragma unroll
            for (int i = 0; i < 2; i++)
                #pragma unroll
                for (int j = 0; j < 4; j++)
                    wmma::store_matrix_sync(
                        sm.O + (wm * 32 + i * 16) * 128 + wn * 64 + j * 16,
                        o[i][j], 128, wmma::mem_row_major);
        }
        __syncthreads();
    }

    // writeout: contiguous 8x2048 block, normalized by 1/l[row]
    #pragma unroll
    for (int t = 0; t < 16; t++) {
        int slot = tid + t * 256;
        float inv = 1.0f / sm.l[slot >> 5];
        float4 o4 = *(float4*)(sm.O + slot * 4);
        o4.x *= inv; o4.y *= inv; o4.z *= inv; o4.w *= inv;
        *(float4*)(AO + qbase + (size_t)slot * 4) = o4;
    }
}

// ---------------------------------------------------------------------------
extern "C" void kernel_launch(void* const* d_in, const int* in_sizes, int n_in,
                              void* d_out, int out_size)
{
    (void)in_sizes; (void)n_in; (void)out_size;
    const float* q  = (const float*)d_in[0];
    const float* k  = (const float*)d_in[1];
    const float* v  = (const float*)d_in[2];
    const float* Wq = (const float*)d_in[3];
    const float* bq = (const float*)d_in[4];
    const float* Wk = (const float*)d_in[5];
    const float* bk = (const float*)d_in[6];
    const float* Wv = (const float*)d_in[7];
    const float* bv = (const float*)d_in[8];
    const float* Wo = (const float*)d_in[9];
    const float* bo = (const float*)d_in[10];
    float* out = (float*)d_out;

    void* p;
    cudaGetSymbolAddress(&p, g_qp); float* qp = (float*)p;
    cudaGetSymbolAddress(&p, g_kp); float* kp = (float*)p;
    cudaGetSymbolAddress(&p, g_vp); float* vp = (float*)p;
    cudaGetSymbolAddress(&p, g_ao); float* ao = (float*)p;

    cudaFuncSetAttribute(fa_kernel, cudaFuncAttributeMaxDynamicSharedMemorySize,
                         (int)sizeof(FASmem));

    const int M = B_ * S_;   // 8192

    // Q/K/V projections
    gemm_tf32<<<dim3(D_  / GBN, M / GBM), 256>>>(q, Wq, bq, qp, M, D_,  D_);
    gemm_tf32<<<dim3(DH_ / GBN, M / GBM), 256>>>(k, Wk, bk, kp, M, DH_, D_);
    gemm_tf32<<<dim3(DH_ / GBN, M / GBM), 256>>>(v, Wv, bv, vp, M, DH_, D_);

    // fused attention: grid = (s-tiles of 8, batch); heads folded into M
    fa_kernel<<<dim3(S_ / 8, B_), 256, sizeof(FASmem)>>>(qp, kp, vp, ao);

    // output projection
    gemm_tf32<<<dim3(D_ / GBN, M / GBM), 256>>>(ao, Wo, bo, out, M, D_, D_);
}

// round 12
// speedup vs baseline: 1.7979x; 1.7979x over previous
#include <cuda_runtime.h>
#include <cuda_pipeline.h>
#include <mma.h>
#include <math.h>

using namespace nvcuda;

#define B_  4
#define S_  2048
#define D_  2048
#define H_  16
#define DH_ 128

// Scratch (allocation-free rule: __device__ globals)
__device__ float g_qp[(size_t)B_ * S_ * D_];    // Q projection (tf32-rounded, pre-scaled)
__device__ float g_kp[(size_t)B_ * S_ * DH_];   // K projection (tf32-rounded)
__device__ float g_vp[(size_t)B_ * S_ * DH_];   // V projection (tf32-rounded)
__device__ float g_ao[(size_t)B_ * S_ * D_];    // attention out [B*S, D]

// ---------------------------------------------------------------------------
// tf32 GEMM body: C[M,N] = (A[M,K] @ B[K,N] + bias[N]) * outScale (opt. round)
// Block tile 128x128, K-chunk 32, 256 threads (8 warps, 2x4 grid, warp tile
// 64x32 = 4x2 m16n16k8 frags -> 6 fragment loads per 8 MMAs).
// cp.async double-buffered; padded smem strides (A:36, B:132).
// Requires M%128==0, N%128==0, K%32==0 (holds for all 5 GEMMs).
// ---------------------------------------------------------------------------
#define BM 128
#define BN 128
#define BK 32
#define ALD 36
#define BLD 132
#define ASTG (BM * ALD)          // 4608 floats
#define BSTG (BK * BLD)          // 4224 floats
#define STG  (ASTG + BSTG)       // 8832 floats
#define GEMM_SMEM (2 * STG * 4)  // 70656 bytes (also covers 128x132 epilogue)

__device__ __forceinline__ void gemm_body(
    const float* __restrict__ A, const float* __restrict__ Bm,
    const float* __restrict__ bias, float* __restrict__ C,
    int M, int N, int K, float outScale, int roundOut)
{
    extern __shared__ __align__(16) float smem[];

    const int tid  = threadIdx.x;
    const int warp = tid >> 5;
    const int wm   = warp & 1;    // 0..1 -> 64-row strip
    const int wn   = warp >> 1;   // 0..3 -> 32-col strip
    const int m0   = blockIdx.y * BM;
    const int n0   = blockIdx.x * BN;

    const int ar = tid >> 3, ac4 = tid & 7;     // A: 128x32, 8 float4/row
    const int br = tid >> 5, bc4 = tid & 31;    // B: 32x128, 32 float4/row

    auto prefetch = [&](int stage, int k0) {
        float* sA = smem + stage * STG;
        float* sB = sA + ASTG;
        #pragma unroll
        for (int t = 0; t < 4; t++) {
            int r = ar + t * 32;
            __pipeline_memcpy_async(sA + r * ALD + ac4 * 4,
                                    A + (size_t)(m0 + r) * K + k0 + ac4 * 4, 16);
        }
        #pragma unroll
        for (int t = 0; t < 4; t++) {
            int r = br + t * 8;
            __pipeline_memcpy_async(sB + r * BLD + bc4 * 4,
                                    Bm + (size_t)(k0 + r) * N + n0 + bc4 * 4, 16);
        }
        __pipeline_commit();
    };

    wmma::fragment<wmma::accumulator, 16, 16, 8, float> c[4][2];
    #pragma unroll
    for (int i = 0; i < 4; i++)
        #pragma unroll
        for (int j = 0; j < 2; j++)
            wmma::fill_fragment(c[i][j], 0.0f);

    const int nIter = K / BK;
    prefetch(0, 0);

    for (int it = 0; it < nIter; it++) {
        const int cur = it & 1;
        if (it + 1 < nIter) prefetch(cur ^ 1, (it + 1) * BK);
        __pipeline_wait_prior((it + 1 < nIter) ? 1 : 0);
        __syncthreads();

        const float* sA = smem + cur * STG;
        const float* sB = sA + ASTG;

        #pragma unroll
        for (int kk = 0; kk < BK; kk += 8) {
            wmma::fragment<wmma::matrix_a, 16, 16, 8, wmma::precision::tf32, wmma::row_major> a[4];
            wmma::fragment<wmma::matrix_b, 16, 16, 8, wmma::precision::tf32, wmma::row_major> b[2];
            #pragma unroll
            for (int i = 0; i < 4; i++) {
                wmma::load_matrix_sync(a[i], sA + (wm * 64 + i * 16) * ALD + kk, ALD);
                #pragma unroll
                for (int e = 0; e < a[i].num_elements; e++)
                    a[i].x[e] = wmma::__float_to_tf32(a[i].x[e]);
            }
            #pragma unroll
            for (int j = 0; j < 2; j++) {
                wmma::load_matrix_sync(b[j], sB + kk * BLD + wn * 32 + j * 16, BLD);
                #pragma unroll
                for (int e = 0; e < b[j].num_elements; e++)
                    b[j].x[e] = wmma::__float_to_tf32(b[j].x[e]);
            }
            #pragma unroll
            for (int i = 0; i < 4; i++)
                #pragma unroll
                for (int j = 0; j < 2; j++)
                    wmma::mma_sync(c[i][j], a[i], b[j], c[i][j]);
        }
        __syncthreads();
    }

    // epilogue: frags -> smem (stride BLD) -> coalesced stores with bias
    #pragma unroll
    for (int i = 0; i < 4; i++)
        #pragma unroll
        for (int j = 0; j < 2; j++)
            wmma::store_matrix_sync(smem + (wm * 64 + i * 16) * BLD + wn * 32 + j * 16,
                                    c[i][j], BLD, wmma::mem_row_major);
    __syncthreads();
    #pragma unroll
    for (int t = 0; t < 16; t++) {
        int slot = tid + t * 256;            // 4096 float4
        int r = slot >> 5, c4 = slot & 31;
        float4 val = *(float4*)(smem + r * BLD + c4 * 4);
        const float* bp = bias + n0 + c4 * 4;
        val.x = (val.x + bp[0]) * outScale;
        val.y = (val.y + bp[1]) * outScale;
        val.z = (val.z + bp[2]) * outScale;
        val.w = (val.w + bp[3]) * outScale;
        if (roundOut) {
            val.x = wmma::__float_to_tf32(val.x);
            val.y = wmma::__float_to_tf32(val.y);
            val.z = wmma::__float_to_tf32(val.z);
            val.w = wmma::__float_to_tf32(val.w);
        }
        *(float4*)(C + (size_t)(m0 + r) * N + n0 + c4 * 4) = val;
    }
}

__global__ __launch_bounds__(256, 2) void gemm_tf32(
    const float* __restrict__ A, const float* __restrict__ Bm,
    const float* __restrict__ bias, float* __restrict__ C,
    int M, int N, int K, float outScale, int roundOut)
{
    gemm_body(A, Bm, bias, C, M, N, K, outScale, roundOut);
}

// Fused K-proj + V-proj: both are [8192,2048]@[2048,128], only 64 CTAs each.
// gridDim.z = 2 runs them concurrently (identical math to two launches).
__global__ __launch_bounds__(256, 2) void gemm_kv(
    const float* __restrict__ k, const float* __restrict__ Wk,
    const float* __restrict__ bk, float* __restrict__ kp,
    const float* __restrict__ v, const float* __restrict__ Wv,
    const float* __restrict__ bv, float* __restrict__ vp)
{
    if (blockIdx.z == 0)
        gemm_body(k, Wk, bk, kp, B_ * S_, DH_, D_, 1.0f, 1);
    else
        gemm_body(v, Wv, bv, vp, B_ * S_, DH_, D_, 1.0f, 1);
}

// ---------------------------------------------------------------------------
// Fused flash attention exploiting MQA (K/V shared across H=16 heads).
// M-tile = 128 rows = 8 consecutive s x 16 heads (contiguous 8x2048 Q block).
// 512 threads (16 warps, warp tile 32 rows x {16 cols QK / 32 cols PV}).
// O accumulator lives in registers across the whole K loop; per-row alpha
// rescale applied to fragment elements (sm_80+ f32 accum layout:
// x[e] row = quad + 8*((e>>1)&1)).
// Q/K/V already tf32-rounded (and Q pre-scaled) by projection epilogues;
// P rounded at softmax write -> no in-loop conversions.
// K double-buffered, V prefetched per-iter via cp.async. Padded strides.
// ---------------------------------------------------------------------------
#define QLD 132
#define KLD 132
#define VLD 132
#define SLD 68

struct FASmem {
    float Q[128 * QLD];       // 67584 B
    float K[2][64 * KLD];     // 67584 B
    float V[64 * VLD];        // 33792 B
    float S[128 * SLD];       // 34816 B
    float m[128];
    float l[128];
    float alpha[128];
};                             // 205312 B

__global__ __launch_bounds__(512, 1) void fa_kernel(
    const float* __restrict__ Qp, const float* __restrict__ Kp,
    const float* __restrict__ Vp, float* __restrict__ AO)
{
    extern __shared__ __align__(16) char smraw[];
    FASmem& sm = *reinterpret_cast<FASmem*>(smraw);

    const int tid  = threadIdx.x;
    const int warp = tid >> 5;
    const int lane = tid & 31;
    const int quad = lane >> 2;
    const int wm   = warp >> 2;   // 0..3 -> 32-row strip
    const int wn   = warp & 3;    // 0..3
    const int s0   = blockIdx.x * 8;
    const int b    = blockIdx.y;

    const size_t qbase = (size_t)(b * S_ + s0) * D_;

    // load Q tile: contiguous 8x2048 = 4096 float4, 8 per thread (padded rows)
    #pragma unroll
    for (int t = 0; t < 8; t++) {
        int slot = tid + t * 512;
        int r = slot >> 5, c4 = slot & 31;
        *(float4*)(sm.Q + r * QLD + c4 * 4) = *(const float4*)(Qp + qbase + (size_t)slot * 4);
    }
    if (tid < 128) { sm.m[tid] = -INFINITY; sm.l[tid] = 0.0f; }

    auto stageK = [&](int st, int kt) {
        const float* src = Kp + (size_t)(b * S_ + kt) * DH_;
        float* dst = sm.K[st];
        #pragma unroll
        for (int t = 0; t < 4; t++) {
            int slot = tid + t * 512;
            int r = slot >> 5, c4 = slot & 31;
            __pipeline_memcpy_async(dst + r * KLD + c4 * 4, src + (size_t)slot * 4, 16);
        }
        __pipeline_commit();
    };
    auto stageV = [&](int kt) {
        const float* src = Vp + (size_t)(b * S_ + kt) * DH_;
        #pragma unroll
        for (int t = 0; t < 4; t++) {
            int slot = tid + t * 512;
            int r = slot >> 5, c4 = slot & 31;
            __pipeline_memcpy_async(sm.V + r * VLD + c4 * 4, src + (size_t)slot * 4, 16);
        }
        __pipeline_commit();
    };

    // persistent O accumulator: warp strip 32 rows x 32 cols -> 2x2 frags
    wmma::fragment<wmma::accumulator, 16, 16, 8, float> o[2][2];
    #pragma unroll
    for (int i = 0; i < 2; i++)
        #pragma unroll
        for (int j = 0; j < 2; j++)
            wmma::fill_fragment(o[i][j], 0.0f);

    stageK(0, 0);

    for (int it = 0; it < S_ / 64; it++) {
        const int cur = it & 1;
        const int kt  = it * 64;

        __pipeline_wait_prior(0);   // K[cur] landed (this thread)
        __syncthreads();            // all threads' copies visible; prev PV done
        stageV(kt);                 // overlaps QK + softmax
        if (it + 1 < S_ / 64) stageK(cur ^ 1, kt + 64);

        // S = Q @ K^T : warp computes 32x16 (2x1 frags)
        {
            const float* Kc = sm.K[cur];
            wmma::fragment<wmma::accumulator, 16, 16, 8, float> s[2];
            wmma::fill_fragment(s[0], 0.0f);
            wmma::fill_fragment(s[1], 0.0f);
            #pragma unroll
            for (int kk = 0; kk < 128; kk += 8) {
                wmma::fragment<wmma::matrix_a, 16, 16, 8, wmma::precision::tf32, wmma::row_major> a[2];
                wmma::load_matrix_sync(a[0], sm.Q + (wm * 32) * QLD + kk, QLD);
                wmma::load_matrix_sync(a[1], sm.Q + (wm * 32 + 16) * QLD + kk, QLD);
                wmma::fragment<wmma::matrix_b, 16, 16, 8, wmma::precision::tf32, wmma::col_major> bf;
                wmma::load_matrix_sync(bf, Kc + (wn * 16) * KLD + kk, KLD);
                wmma::mma_sync(s[0], a[0], bf, s[0]);
                wmma::mma_sync(s[1], a[1], bf, s[1]);
            }
            wmma::store_matrix_sync(sm.S + (wm * 32) * SLD + wn * 16,      s[0], SLD, wmma::mem_row_major);
            wmma::store_matrix_sync(sm.S + (wm * 32 + 16) * SLD + wn * 16, s[1], SLD, wmma::mem_row_major);
        }
        __syncthreads();

        // online softmax: 4 threads/row, 16 cols each, shfl reductions
        {
            const int row = tid >> 2, part = tid & 3;
            float* srow = sm.S + row * SLD + part * 16;
            float pm = -INFINITY;
            #pragma unroll
            for (int c = 0; c < 16; c++) pm = fmaxf(pm, srow[c]);
            pm = fmaxf(pm, __shfl_xor_sync(0xffffffffu, pm, 1));
            pm = fmaxf(pm, __shfl_xor_sync(0xffffffffu, pm, 2));
            const float mold = sm.m[row];
            const float mnew = fmaxf(mold, pm);
            float psum = 0.f;
            #pragma unroll
            for (int c = 0; c < 16; c++) {
                float e = wmma::__float_to_tf32(__expf(srow[c] - mnew));
                srow[c] = e;
                psum += e;
            }
            psum += __shfl_xor_sync(0xffffffffu, psum, 1);
            psum += __shfl_xor_sync(0xffffffffu, psum, 2);
            if (part == 0) {
                float al = __expf(mold - mnew);
                sm.alpha[row] = al;
                sm.l[row] = sm.l[row] * al + psum;
                sm.m[row] = mnew;
            }
        }

        __pipeline_wait_prior((it + 1 < S_ / 64) ? 1 : 0);   // V landed; K[next] may fly
        __syncthreads();                                      // P/alpha/V visible to all

        // O = O*alpha(row) + P @ V   (alpha applied per fragment row)
        #pragma unroll
        for (int i = 0; i < 2; i++) {
            int r0 = wm * 32 + i * 16 + quad;
            float a0 = sm.alpha[r0];
            float a1 = sm.alpha[r0 + 8];
            #pragma unroll
            for (int j = 0; j < 2; j++) {
                o[i][j].x[0] *= a0; o[i][j].x[1] *= a0;
                o[i][j].x[2] *= a1; o[i][j].x[3] *= a1;
                o[i][j].x[4] *= a0; o[i][j].x[5] *= a0;
                o[i][j].x[6] *= a1; o[i][j].x[7] *= a1;
            }
        }
        #pragma unroll
        for (int kk = 0; kk < 64; kk += 8) {
            wmma::fragment<wmma::matrix_a, 16, 16, 8, wmma::precision::tf32, wmma::row_major> a[2];
            wmma::load_matrix_sync(a[0], sm.S + (wm * 32) * SLD + kk, SLD);
            wmma::load_matrix_sync(a[1], sm.S + (wm * 32 + 16) * SLD + kk, SLD);
            #pragma unroll
            for (int j = 0; j < 2; j++) {
                wmma::fragment<wmma::matrix_b, 16, 16, 8, wmma::precision::tf32, wmma::row_major> bf;
                wmma::load_matrix_sync(bf, sm.V + kk * VLD + wn * 32 + j * 16, VLD);
                wmma::mma_sync(o[0][j], a[0], bf, o[0][j]);
                wmma::mma_sync(o[1][j], a[1], bf, o[1][j]);
            }
        }
    }

    // writeout: frags -> sm.Q (Q dead) -> normalized float4 stores
    #pragma unroll
    for (int i = 0; i < 2; i++)
        #pragma unroll
        for (int j = 0; j < 2; j++)
            wmma::store_matrix_sync(sm.Q + (wm * 32 + i * 16) * QLD + wn * 32 + j * 16,
                                    o[i][j], QLD, wmma::mem_row_major);
    __syncthreads();
    #pragma unroll
    for (int t = 0; t < 8; t++) {
        int slot = tid + t * 512;
        int r = slot >> 5, c4 = slot & 31;
        float inv = 1.0f / sm.l[r];
        float4 o4 = *(float4*)(sm.Q + r * QLD + c4 * 4);
        o4.x *= inv; o4.y *= inv; o4.z *= inv; o4.w *= inv;
        *(float4*)(AO + qbase + (size_t)slot * 4) = o4;
    }
}

// ---------------------------------------------------------------------------
extern "C" void kernel_launch(void* const* d_in, const int* in_sizes, int n_in,
                              void* d_out, int out_size)
{
    (void)in_sizes; (void)n_in; (void)out_size;
    const float* q  = (const float*)d_in[0];
    const float* k  = (const float*)d_in[1];
    const float* v  = (const float*)d_in[2];
    const float* Wq = (const float*)d_in[3];
    const float* bq = (const float*)d_in[4];
    const float* Wk = (const float*)d_in[5];
    const float* bk = (const float*)d_in[6];
    const float* Wv = (const float*)d_in[7];
    const float* bv = (const float*)d_in[8];
    const float* Wo = (const float*)d_in[9];
    const float* bo = (const float*)d_in[10];
    float* out = (float*)d_out;

    void* p;
    cudaGetSymbolAddress(&p, g_qp); float* qp = (float*)p;
    cudaGetSymbolAddress(&p, g_kp); float* kp = (float*)p;
    cudaGetSymbolAddress(&p, g_vp); float* vp = (float*)p;
    cudaGetSymbolAddress(&p, g_ao); float* ao = (float*)p;

    cudaFuncSetAttribute(gemm_tf32, cudaFuncAttributeMaxDynamicSharedMemorySize, GEMM_SMEM);
    cudaFuncSetAttribute(gemm_kv,  cudaFuncAttributeMaxDynamicSharedMemorySize, GEMM_SMEM);
    cudaFuncSetAttribute(fa_kernel, cudaFuncAttributeMaxDynamicSharedMemorySize,
                         (int)sizeof(FASmem));

    const int M = B_ * S_;   // 8192
    const float qscale = 0.08838834764831845f;   // 1/sqrt(128)

    // Projections: Q pre-scaled; Q/K/V tf32-rounded for the attention MMAs
    gemm_tf32<<<dim3(D_ / BN, M / BM), 256, GEMM_SMEM>>>(q, Wq, bq, qp, M, D_, D_, qscale, 1);
    // K-proj and V-proj fused into one launch (each is only 64 CTAs)
    gemm_kv<<<dim3(DH_ / BN, M / BM, 2), 256, GEMM_SMEM>>>(k, Wk, bk, kp, v, Wv, bv, vp);

    // fused attention: grid = (s-tiles of 8, batch); heads folded into M
    fa_kernel<<<dim3(S_ / 8, B_), 512, sizeof(FASmem)>>>(qp, kp, vp, ao);

    // output projection (full fp32 output)
    gemm_tf32<<<dim3(D_ / BN, M / BM), 256, GEMM_SMEM>>>(ao, Wo, bo, out, M, D_, D_, 1.0f, 0);
}